// round 12
// baseline (speedup 1.0000x reference)
#include <cuda_runtime.h>
#include <cuda_bf16.h>
#include <math.h>
#include <stdint.h>

#define BQ   16
#define TT   1000
#define MEL  80
#define HID  512
#define NCLS 64
#define NROW (BQ*TT)

#define CLN  8       // CTAs per cluster  (8 clusters x 8 CTAs = 64 -- proven placement)
#define NCTA 64
#define BPC  2       // batch elements per cluster

#define WROWB 1040u                 // bf16 row stride bytes (1024 + 16 pad)
#define WMATB (64u*WROWB)           // 66560 B per matrix slice
#define DYNSM (2u*WMATB)            // 133120 B

// ---------------- scratch (static device globals; no allocations) ----------------
__device__ float g_be0[NROW*HID];
__device__ float g_be1[NROW*HID];
__device__ float g_h1 [NROW*HID];
__device__ float g_xs1[NROW];

__device__ __forceinline__ float sigm(float x){ return 1.0f/(1.0f+expf(-x)); }

__device__ __forceinline__ uint32_t smem_u32(const void* p){
  uint32_t a;
  asm("{ .reg .u64 t; cvta.to.shared.u64 t, %1; cvt.u32.u64 %0, t; }" : "=r"(a) : "l"(p));
  return a;
}
__device__ __forceinline__ uint32_t mapa32(uint32_t laddr, uint32_t rnk){
  uint32_t ra;
  asm("mapa.shared::cluster.u32 %0, %1, %2;" : "=r"(ra) : "r"(laddr), "r"(rnk));
  return ra;
}
__device__ __forceinline__ void st_clu_v4(uint32_t ra, float4 v){
  asm volatile("st.shared::cluster.v4.f32 [%0], {%1,%2,%3,%4};"
               :: "r"(ra), "f"(v.x), "f"(v.y), "f"(v.z), "f"(v.w) : "memory");
}
__device__ __forceinline__ void st_clu_f32(uint32_t ra, float v){
  asm volatile("st.shared::cluster.f32 [%0], %1;" :: "r"(ra), "f"(v) : "memory");
}
#define CLUSTER_ARRIVE() asm volatile("barrier.cluster.arrive.aligned;" ::: "memory")
#define CLUSTER_WAIT()   asm volatile("barrier.cluster.wait.aligned;"   ::: "memory")

// permuted float4-group position for x buffers: group g (=k/4) -> pos
__host__ __device__ __forceinline__ int xpos(int g){
  int j = g>>1;
  return ((j>>4)<<5) + ((g&1)<<4) + (j&15);
}

// ---------------- be0 = clip(feats/||feats||) @ B0^T ; xs1 = ||be0|| ----------------
__global__ __launch_bounds__(256) void k_be0(const float* __restrict__ feats,
                                             const float* __restrict__ B0){
  __shared__ float xn[16][MEL];
  __shared__ float snorm[16];
  __shared__ float sxs[16];
  int tid = threadIdx.x;
  int row0 = blockIdx.x*16;
  for (int i=tid;i<16*MEL;i+=256)
    xn[i/MEL][i%MEL] = feats[row0*MEL + i];
  __syncthreads();
  if (tid<16){
    float s=0.f;
    #pragma unroll
    for (int k=0;k<MEL;k++){ float v=xn[tid][k]; s+=v*v; }
    sxs[tid]=fmaxf(sqrtf(s),1e-6f);
    snorm[tid]=0.f;
  }
  __syncthreads();
  for (int i=tid;i<16*MEL;i+=256){
    int r=i/MEL;
    float v = xn[r][i%MEL]/sxs[r];
    xn[r][i%MEL] = fminf(fmaxf(v,-1.f),1.f);
  }
  __syncthreads();
  int n0=tid, n1=tid+256;
  float a0[16], a1_[16];
  #pragma unroll
  for (int r=0;r<16;r++){ a0[r]=0.f; a1_[r]=0.f; }
  for (int k=0;k<MEL;k+=4){
    float4 w0 = *(const float4*)&B0[n0*MEL+k];
    float4 w1 = *(const float4*)&B0[n1*MEL+k];
    #pragma unroll
    for (int r=0;r<16;r++){
      float4 x = *(const float4*)&xn[r][k];
      a0 [r] += w0.x*x.x + w0.y*x.y + w0.z*x.z + w0.w*x.w;
      a1_[r] += w1.x*x.x + w1.y*x.y + w1.z*x.z + w1.w*x.w;
    }
  }
  #pragma unroll
  for (int r=0;r<16;r++){
    g_be0[(row0+r)*HID+n0]=a0[r];
    g_be0[(row0+r)*HID+n1]=a1_[r];
    atomicAdd(&snorm[r], a0[r]*a0[r] + a1_[r]*a1_[r]);
  }
  __syncthreads();
  if (tid<16) g_xs1[row0+tid] = fmaxf(sqrtf(snorm[tid]),1e-6f);
}

// ---------------- be1 = clip(be0/xs1) @ B1^T ----------------
__global__ __launch_bounds__(256) void k_be1(const float* __restrict__ B1){
  __shared__ float xn[16][HID];
  __shared__ float sxs[16];
  int tid=threadIdx.x;
  int row0=blockIdx.x*16;
  if (tid<16) sxs[tid]=g_xs1[row0+tid];
  __syncthreads();
  for (int i=tid;i<16*HID;i+=256){
    int r=i>>9;
    float v = g_be0[row0*HID + i]/sxs[r];
    xn[r][i&511] = fminf(fmaxf(v,-1.f),1.f);
  }
  __syncthreads();
  int n0=tid, n1=tid+256;
  float a0[16], a1_[16];
  #pragma unroll
  for (int r=0;r<16;r++){ a0[r]=0.f; a1_[r]=0.f; }
  for (int k=0;k<HID;k+=4){
    float4 w0 = *(const float4*)&B1[n0*HID+k];
    float4 w1 = *(const float4*)&B1[n1*HID+k];
    #pragma unroll
    for (int r=0;r<16;r++){
      float4 x = *(const float4*)&xn[r][k];
      a0 [r] += w0.x*x.x + w0.y*x.y + w0.z*x.z + w0.w*x.w;
      a1_[r] += w1.x*x.x + w1.y*x.y + w1.z*x.z + w1.w*x.w;
    }
  }
  #pragma unroll
  for (int r=0;r<16;r++){
    g_be1[(row0+r)*HID+n0]=a0[r];
    g_be1[(row0+r)*HID+n1]=a1_[r];
  }
}

// ---------------- serial recurrence: 4-phase pipelined cluster barriers -----------
// CTA `rank` owns rows [rank*64,+64). Weights bf16 in smem. Per step, 4 phases
// (b0-C1, b1-C1, b0-W1, b1-W1); each phase: dot, epilogue, DSMEM push, then
// WAIT(previous round) + ARRIVE(this round). Every wait is preceded by a full
// phase of independent work since its arrive, so barrier latency is hidden.
__device__ __forceinline__ void dot_phase(const uint8_t* __restrict__ wsm,
                                          const uint8_t* __restrict__ xb,
                                          int rg, int kq, float* __restrict__ pout){
  const uint8_t* wr = wsm + (unsigned)(rg*4)*WROWB + (unsigned)kq*16u;
  float acc[4] = {0.f,0.f,0.f,0.f};
  #pragma unroll
  for (int m=0;m<4;m++){
    float4 x0 = *(const float4*)(xb + (m*32+kq)*16);
    float4 x1 = *(const float4*)(xb + (m*32+16+kq)*16);
    #pragma unroll
    for (int r=0;r<4;r++){
      uint4 w = *(const uint4*)(wr + (unsigned)r*WROWB + (unsigned)m*256u);
      float w0=__uint_as_float(w.x<<16), w1=__uint_as_float(w.x&0xffff0000u);
      float w2=__uint_as_float(w.y<<16), w3=__uint_as_float(w.y&0xffff0000u);
      float w4=__uint_as_float(w.z<<16), w5=__uint_as_float(w.z&0xffff0000u);
      float w6=__uint_as_float(w.w<<16), w7=__uint_as_float(w.w&0xffff0000u);
      acc[r] += w0*x0.x + w1*x0.y + w2*x0.z + w3*x0.w
              + w4*x1.x + w5*x1.y + w6*x1.z + w7*x1.w;
    }
  }
  #pragma unroll
  for (int off=8; off; off>>=1)
    #pragma unroll
    for (int j=0;j<4;j++) acc[j] += __shfl_down_sync(0xffffffffu, acc[j], off);
  if (kq==0){
    #pragma unroll
    for (int j=0;j<4;j++) pout[rg*4+j] = acc[j];
  }
}

__global__ __launch_bounds__(256,1) __cluster_dims__(CLN,1,1)
void k_serial(const float* __restrict__ C1, const float* __restrict__ W1,
              const float* __restrict__ a1, const float* __restrict__ tau,
              const float* __restrict__ gam){
  extern __shared__ __align__(16) uint8_t dynsm[];
  uint8_t* wsmC = dynsm;                 // [64][WROWB] bf16
  uint8_t* wsmW = dynsm + WMATB;

  __shared__ __align__(16) float hbufP[BPC][HID];    // permuted h   (remote-written)
  __shared__ __align__(16) float ebufP[BPC][HID];    // permuted err (remote-written)
  __shared__ __align__(16) float estage[64];
  __shared__ __align__(16) float hstage[64];
  __shared__ float pout[64];
  __shared__ float narr[BPC][CLN];                   // norm partials (remote-written)
  __shared__ float normloc[2][BPC];                  // ping-pong by step parity
  __shared__ float sa[64];

  const int tid  = threadIdx.x;
  const int rank = blockIdx.x & (CLN-1);
  const int bg0  = (blockIdx.x / CLN) * BPC;         // global batch of b0
  const int rg   = tid >> 4, kq = tid & 15;
  const float tauv = __ldg(&tau[0]), gamv = __ldg(&gam[0]);

  // -------- prologue: convert weight slices fp32 -> bf16 smem --------
  for (int i=tid; i<64*128; i+=256){
    int r=i>>7, q=i&127;
    float4 vc = __ldg((const float4*)&C1[(rank*64+r)*HID + q*4]);
    float4 vw = __ldg((const float4*)&W1[(rank*64+r)*HID + q*4]);
    __nv_bfloat162 c0 = __floats2bfloat162_rn(vc.x, vc.y);
    __nv_bfloat162 c1 = __floats2bfloat162_rn(vc.z, vc.w);
    __nv_bfloat162 w0 = __floats2bfloat162_rn(vw.x, vw.y);
    __nv_bfloat162 w1 = __floats2bfloat162_rn(vw.z, vw.w);
    uint2 uc; uc.x = *(uint32_t*)&c0; uc.y = *(uint32_t*)&c1;
    uint2 uw; uw.x = *(uint32_t*)&w0; uw.y = *(uint32_t*)&w1;
    *(uint2*)(wsmC + (unsigned)r*WROWB + (unsigned)q*8u) = uc;
    *(uint2*)(wsmW + (unsigned)r*WROWB + (unsigned)q*8u) = uw;
  }
  for (int i=tid;i<BPC*HID;i+=256) (&hbufP[0][0])[i]=0.f;
  if (tid<2*BPC) (&normloc[0][0])[tid]=0.f;
  if (tid<64)  sa[tid] = sigm(__ldg(&a1[rank*64+tid]));
  __syncthreads();
  CLUSTER_ARRIVE(); CLUSTER_WAIT();     // init visible cluster-wide

  const uint32_t a_ebuf = smem_u32(&ebufP[0][0]);
  const uint32_t a_hbuf = smem_u32(&hbufP[0][0]);
  const uint32_t a_narr = smem_u32(&narr[0][0]);

  const uint32_t wp = tid >> 5, lane = tid & 31;     // push: warp wp -> dest CTA wp
  const uint32_t xoff0 = (uint32_t)(0*HID + xpos(rank*16 + (int)(lane&15))*4)*4u;
  const uint32_t xoff1 = (uint32_t)(1*HID + xpos(rank*16 + (int)(lane&15))*4)*4u;
  const uint32_t raE0 = mapa32(a_ebuf + xoff0, wp);
  const uint32_t raE1 = mapa32(a_ebuf + xoff1, wp);
  const uint32_t raH0 = mapa32(a_hbuf + xoff0, wp);
  const uint32_t raH1 = mapa32(a_hbuf + xoff1, wp);
  const uint32_t raN0 = mapa32(a_narr + (uint32_t)(0*CLN + rank)*4u, wp);
  const uint32_t raN1 = mapa32(a_narr + (uint32_t)(1*CLN + rank)*4u, wp);
  // permuted index of own h element (epilogue-2 hold read), per b
  const int hk    = rank*64 + tid;                   // valid for tid<64
  const int hidx0 = 0*HID + xpos(hk>>2)*4 + (tid&3);
  const int hidx1 = 1*HID + xpos(hk>>2)*4 + (tid&3);

  for (int t=0;t<TT;t++){
    const int par = t&1;
    float xs0=1.f, be00=0.f, be10=0.f;
    float xs1_=1.f, be01=0.f, be11=0.f;

    // ======== phase 0: b0, p = h @ C1^T, err, norm ========
    if (tid<64){
      xs0  = __ldg(&g_xs1[bg0*TT+t]);
      be00 = __ldg(&g_be0[(bg0*TT+t)*HID + rank*64 + tid]);
      be10 = __ldg(&g_be1[(bg0*TT+t)*HID + rank*64 + tid]);
    }
    dot_phase(wsmC, (const uint8_t*)&hbufP[0][0], rg, kq, pout);
    __syncthreads();
    if (tid<64){
      float e = be00 - tanhf(pout[tid])*xs0;
      estage[tid] = e;
      float q = e*e;
      #pragma unroll
      for (int off=16; off; off>>=1) q += __shfl_xor_sync(0xffffffffu,q,off);
      if ((tid&31)==0) atomicAdd(&normloc[par][0], q);
    }
    __syncthreads();
    if (lane<16)       st_clu_v4(raE0, ((const float4*)estage)[lane]);
    else if (lane==16) st_clu_f32(raN0, normloc[par][0]);
    if (t) CLUSTER_WAIT();
    CLUSTER_ARRIVE();

    // ======== phase 1: b1, p = h @ C1^T, err, norm ========
    if (tid<64){
      xs1_ = __ldg(&g_xs1[(bg0+1)*TT+t]);
      be01 = __ldg(&g_be0[((bg0+1)*TT+t)*HID + rank*64 + tid]);
      be11 = __ldg(&g_be1[((bg0+1)*TT+t)*HID + rank*64 + tid]);
    }
    dot_phase(wsmC, (const uint8_t*)&hbufP[1][0], rg, kq, pout);
    __syncthreads();
    if (tid<64){
      float e = be01 - tanhf(pout[tid])*xs1_;
      estage[tid] = e;
      float q = e*e;
      #pragma unroll
      for (int off=16; off; off>>=1) q += __shfl_xor_sync(0xffffffffu,q,off);
      if ((tid&31)==0) atomicAdd(&normloc[par][1], q);
    }
    __syncthreads();
    if (lane<16)       st_clu_v4(raE1, ((const float4*)estage)[lane]);
    else if (lane==16) st_clu_f32(raN1, normloc[par][1]);
    CLUSTER_WAIT();            // retires round covering e(b0)
    CLUSTER_ARRIVE();

    // ======== phase 2: b0, ee = err @ W1^T, h update ========
    dot_phase(wsmW, (const uint8_t*)&ebufP[0][0], rg, kq, pout);
    __syncthreads();
    if (tid<64){
      float n2 = (narr[0][0]+narr[0][1])+(narr[0][2]+narr[0][3])
               + (narr[0][4]+narr[0][5])+(narr[0][6]+narr[0][7]);
      float rel = fminf(sqrtf(n2)/xs0, 4.0f);
      float s = sigm((rel - tauv)/gamv);
      float hold = (&hbufP[0][0])[hidx0];
      float ih = 0.2f*hold + 0.6f*be10 + 0.2f*s*pout[tid];
      float g = s*sa[tid];
      float hn = hold*(1.f-g) + tanhf(ih)*g;
      hstage[tid] = hn;
      g_h1[(bg0*TT+t)*HID + rank*64 + tid] = hn;
    } else if (tid<64+2){
      normloc[par^1][tid-64] = 0.f;       // reset other-parity slots for t+1
    }
    __syncthreads();
    if (lane<16) st_clu_v4(raH0, ((const float4*)hstage)[lane]);
    CLUSTER_WAIT();            // retires round covering e(b1)
    CLUSTER_ARRIVE();

    // ======== phase 3: b1, ee = err @ W1^T, h update ========
    dot_phase(wsmW, (const uint8_t*)&ebufP[1][0], rg, kq, pout);
    __syncthreads();
    if (tid<64){
      float n2 = (narr[1][0]+narr[1][1])+(narr[1][2]+narr[1][3])
               + (narr[1][4]+narr[1][5])+(narr[1][6]+narr[1][7]);
      float rel = fminf(sqrtf(n2)/xs1_, 4.0f);
      float s = sigm((rel - tauv)/gamv);
      float hold = (&hbufP[0][0])[hidx1];
      float ih = 0.2f*hold + 0.6f*be11 + 0.2f*s*pout[tid];
      float g = s*sa[tid];
      float hn = hold*(1.f-g) + tanhf(ih)*g;
      hstage[tid] = hn;
      g_h1[((bg0+1)*TT+t)*HID + rank*64 + tid] = hn;
    }
    __syncthreads();
    if (lane<16) st_clu_v4(raH1, ((const float4*)hstage)[lane]);
    CLUSTER_WAIT();            // retires round covering h(b0)
    CLUSTER_ARRIVE();
  }
  CLUSTER_WAIT();              // retire final round
}

// ---------------- head: out = [h1, be1] @ head_w^T + head_b ----------------
__global__ __launch_bounds__(256) void k_head(const float* __restrict__ hw,
                                              const float* __restrict__ hb,
                                              float* __restrict__ out){
  __shared__ float sh[8*1024];
  __shared__ float sred[4*8*64];
  int tid=threadIdx.x;
  int row0=blockIdx.x*8;
  for (int i=tid;i<8*1024;i+=256){
    int r=i>>10, j=i&1023;
    sh[i] = (j<512)? g_h1[(row0+r)*HID+j] : g_be1[(row0+r)*HID+(j-512)];
  }
  __syncthreads();
  int c=tid&63, q=tid>>6;
  float acc[8];
  #pragma unroll
  for (int r=0;r<8;r++) acc[r]=0.f;
  for (int k=q*256;k<q*256+256;k+=4){
    float4 w = *(const float4*)&hw[c*1024+k];
    #pragma unroll
    for (int r=0;r<8;r++){
      float4 x = *(const float4*)&sh[r*1024+k];
      acc[r] += w.x*x.x + w.y*x.y + w.z*x.z + w.w*x.w;
    }
  }
  #pragma unroll
  for (int r=0;r<8;r++) sred[(q*8+r)*64+c]=acc[r];
  __syncthreads();
  for (int i=tid;i<8*64;i+=256){
    int r=i>>6, cc=i&63;
    out[(row0+r)*NCLS+cc] = sred[r*64+cc] + sred[(8+r)*64+cc]
                          + sred[(16+r)*64+cc] + sred[(24+r)*64+cc] + __ldg(&hb[cc]);
  }
}

// ---------------- launch ----------------
extern "C" void kernel_launch(void* const* d_in, const int* in_sizes, int n_in,
                              void* d_out, int out_size){
  const float* feats=(const float*)d_in[0];
  const float* B0  =(const float*)d_in[2];
  const float* C1  =(const float*)d_in[7];
  const float* B1  =(const float*)d_in[8];
  const float* W1  =(const float*)d_in[9];
  const float* a1  =(const float*)d_in[10];
  const float* tau1=(const float*)d_in[11];
  const float* gam1=(const float*)d_in[12];
  const float* hw  =(const float*)d_in[13];
  const float* hb  =(const float*)d_in[14];
  float* out=(float*)d_out;

  static int smem_set = 0;
  if (!smem_set){
    cudaFuncSetAttribute(k_serial, cudaFuncAttributeMaxDynamicSharedMemorySize, DYNSM);
    smem_set = 1;
  }

  k_be0   <<<NROW/16,256>>>(feats,B0);
  k_be1   <<<NROW/16,256>>>(B1);
  k_serial<<<NCTA,256,DYNSM>>>(C1,W1,a1,tau1,gam1);
  k_head  <<<NROW/8,256>>>(hw,hb,out);
}

// round 13
// speedup vs baseline: 1.1414x; 1.1414x over previous
#include <cuda_runtime.h>
#include <cuda_bf16.h>
#include <math.h>
#include <stdint.h>

#define BQ   16
#define TT   1000
#define MEL  80
#define HID  512
#define NCLS 64
#define NROW (BQ*TT)

#define CLN  8       // CTAs per cluster  (8 clusters x 8 CTAs = 64 -- proven placement)
#define NCTA 64
#define BPC  2       // batch elements per cluster

// ---------------- scratch (static device globals; no allocations) ----------------
__device__ float g_be0[NROW*HID];
__device__ float g_be1[NROW*HID];
__device__ float g_h1 [NROW*HID];
__device__ float g_xs1[NROW];

__device__ __forceinline__ float sigm(float x){ return 1.0f/(1.0f+expf(-x)); }

__device__ __forceinline__ uint32_t smem_u32(const void* p){
  uint32_t a;
  asm("{ .reg .u64 t; cvta.to.shared.u64 t, %1; cvt.u32.u64 %0, t; }" : "=r"(a) : "l"(p));
  return a;
}
__device__ __forceinline__ void dsmem_st4(uint32_t laddr, uint32_t rnk, float4 v){
  uint32_t ra;
  asm volatile("mapa.shared::cluster.u32 %0, %1, %2;" : "=r"(ra) : "r"(laddr), "r"(rnk));
  asm volatile("st.shared::cluster.v4.f32 [%0], {%1,%2,%3,%4};"
               :: "r"(ra), "f"(v.x), "f"(v.y), "f"(v.z), "f"(v.w) : "memory");
}
__device__ __forceinline__ void dsmem_st1(uint32_t laddr, uint32_t rnk, float v){
  uint32_t ra;
  asm volatile("mapa.shared::cluster.u32 %0, %1, %2;" : "=r"(ra) : "r"(laddr), "r"(rnk));
  asm volatile("st.shared::cluster.f32 [%0], %1;" :: "r"(ra), "f"(v) : "memory");
}
#define CLUSTER_ARRIVE() asm volatile("barrier.cluster.arrive.aligned;" ::: "memory")
#define CLUSTER_WAIT()   asm volatile("barrier.cluster.wait.aligned;"   ::: "memory")

// packed f32x2 helpers (proven in R7)
__device__ __forceinline__ unsigned long long bpack(unsigned lo, unsigned hi){
  unsigned long long r;
  asm("mov.b64 %0, {%1,%2};" : "=l"(r) : "r"(lo), "r"(hi));
  return r;
}
__device__ __forceinline__ void ffma2(unsigned long long& a, unsigned long long w,
                                      unsigned long long x){
  asm("fma.rn.f32x2 %0, %1, %2, %0;" : "+l"(a) : "l"(w), "l"(x));
}
__device__ __forceinline__ float hsum2(unsigned long long a){
  return __uint_as_float((unsigned)(a & 0xffffffffu)) +
         __uint_as_float((unsigned)(a >> 32));
}

// permuted float4-group position for x buffers: group g (=k/4) -> pos
__host__ __device__ __forceinline__ int xpos(int g){
  int j = g>>1;
  return ((j>>4)<<5) + ((g&1)<<4) + (j&15);
}

// ---------------- be0 = clip(feats/||feats||) @ B0^T ; xs1 = ||be0|| ----------------
__global__ __launch_bounds__(256) void k_be0(const float* __restrict__ feats,
                                             const float* __restrict__ B0){
  __shared__ float xn[16][MEL];
  __shared__ float snorm[16];
  __shared__ float sxs[16];
  int tid = threadIdx.x;
  int row0 = blockIdx.x*16;
  for (int i=tid;i<16*MEL;i+=256)
    xn[i/MEL][i%MEL] = feats[row0*MEL + i];
  __syncthreads();
  if (tid<16){
    float s=0.f;
    #pragma unroll
    for (int k=0;k<MEL;k++){ float v=xn[tid][k]; s+=v*v; }
    sxs[tid]=fmaxf(sqrtf(s),1e-6f);
    snorm[tid]=0.f;
  }
  __syncthreads();
  for (int i=tid;i<16*MEL;i+=256){
    int r=i/MEL;
    float v = xn[r][i%MEL]/sxs[r];
    xn[r][i%MEL] = fminf(fmaxf(v,-1.f),1.f);
  }
  __syncthreads();
  int n0=tid, n1=tid+256;
  float a0[16], a1_[16];
  #pragma unroll
  for (int r=0;r<16;r++){ a0[r]=0.f; a1_[r]=0.f; }
  for (int k=0;k<MEL;k+=4){
    float4 w0 = *(const float4*)&B0[n0*MEL+k];
    float4 w1 = *(const float4*)&B0[n1*MEL+k];
    #pragma unroll
    for (int r=0;r<16;r++){
      float4 x = *(const float4*)&xn[r][k];
      a0 [r] += w0.x*x.x + w0.y*x.y + w0.z*x.z + w0.w*x.w;
      a1_[r] += w1.x*x.x + w1.y*x.y + w1.z*x.z + w1.w*x.w;
    }
  }
  #pragma unroll
  for (int r=0;r<16;r++){
    g_be0[(row0+r)*HID+n0]=a0[r];
    g_be0[(row0+r)*HID+n1]=a1_[r];
    atomicAdd(&snorm[r], a0[r]*a0[r] + a1_[r]*a1_[r]);
  }
  __syncthreads();
  if (tid<16) g_xs1[row0+tid] = fmaxf(sqrtf(snorm[tid]),1e-6f);
}

// ---------------- be1 = clip(be0/xs1) @ B1^T ----------------
__global__ __launch_bounds__(256) void k_be1(const float* __restrict__ B1){
  __shared__ float xn[16][HID];
  __shared__ float sxs[16];
  int tid=threadIdx.x;
  int row0=blockIdx.x*16;
  if (tid<16) sxs[tid]=g_xs1[row0+tid];
  __syncthreads();
  for (int i=tid;i<16*HID;i+=256){
    int r=i>>9;
    float v = g_be0[row0*HID + i]/sxs[r];
    xn[r][i&511] = fminf(fmaxf(v,-1.f),1.f);
  }
  __syncthreads();
  int n0=tid, n1=tid+256;
  float a0[16], a1_[16];
  #pragma unroll
  for (int r=0;r<16;r++){ a0[r]=0.f; a1_[r]=0.f; }
  for (int k=0;k<HID;k+=4){
    float4 w0 = *(const float4*)&B1[n0*HID+k];
    float4 w1 = *(const float4*)&B1[n1*HID+k];
    #pragma unroll
    for (int r=0;r<16;r++){
      float4 x = *(const float4*)&xn[r][k];
      a0 [r] += w0.x*x.x + w0.y*x.y + w0.z*x.z + w0.w*x.w;
      a1_[r] += w1.x*x.x + w1.y*x.y + w1.z*x.z + w1.w*x.w;
    }
  }
  #pragma unroll
  for (int r=0;r<16;r++){
    g_be1[(row0+r)*HID+n0]=a0[r];
    g_be1[(row0+r)*HID+n1]=a1_[r];
  }
}

// ---------------- serial recurrence: register-resident bf16 weights ---------------
// R9 skeleton (DSMEM push + split cluster barriers with prefetch in the wait
// windows). Weights live permanently in per-thread registers as bf16 pairs
// (loaded once from global); dot = x-LDS + ALU unpack + fma.rn.f32x2.
__device__ __forceinline__ void dot_reg(const uint4 (&W)[16],
                                        const uint8_t* __restrict__ xb,
                                        int kq, float* __restrict__ out){
  unsigned long long aA[4]={0,0,0,0}, aB[4]={0,0,0,0};
  #pragma unroll
  for (int m=0;m<4;m++){
    ulonglong2 xa0 = *(const ulonglong2*)(xb + (m*32+kq)*16);
    ulonglong2 xa1 = *(const ulonglong2*)(xb + (m*32+16+kq)*16);
    ulonglong2 xb0 = *(const ulonglong2*)(xb + 2048 + (m*32+kq)*16);
    ulonglong2 xb1 = *(const ulonglong2*)(xb + 2048 + (m*32+16+kq)*16);
    #pragma unroll
    for (int r=0;r<4;r++){
      uint4 w = W[m*4+r];
      unsigned long long p0 = bpack(w.x<<16, w.x&0xffff0000u);
      unsigned long long p1 = bpack(w.y<<16, w.y&0xffff0000u);
      unsigned long long p2 = bpack(w.z<<16, w.z&0xffff0000u);
      unsigned long long p3 = bpack(w.w<<16, w.w&0xffff0000u);
      ffma2(aA[r], p0, xa0.x); ffma2(aA[r], p1, xa0.y);
      ffma2(aA[r], p2, xa1.x); ffma2(aA[r], p3, xa1.y);
      ffma2(aB[r], p0, xb0.x); ffma2(aB[r], p1, xb0.y);
      ffma2(aB[r], p2, xb1.x); ffma2(aB[r], p3, xb1.y);
    }
  }
  #pragma unroll
  for (int r=0;r<4;r++){ out[r*2]=hsum2(aA[r]); out[r*2+1]=hsum2(aB[r]); }
}

__global__ __launch_bounds__(256,1) __cluster_dims__(CLN,1,1)
void k_serial(const float* __restrict__ C1, const float* __restrict__ W1,
              const float* __restrict__ a1, const float* __restrict__ tau,
              const float* __restrict__ gam){
  __shared__ __align__(16) float hbufP[BPC][HID];    // permuted h   (remote-written)
  __shared__ __align__(16) float ebufP[BPC][HID];    // permuted err (remote-written)
  __shared__ __align__(16) float estageP[BPC][64];
  __shared__ __align__(16) float hstageP[BPC][64];
  __shared__ float2 pout2[64];
  __shared__ float narr[BPC][CLN];
  __shared__ float normloc[2][BPC];                  // ping-pong by step parity
  __shared__ float sa[64];

  const int tid  = threadIdx.x;
  const int rank = blockIdx.x & (CLN-1);
  const int b0   = (blockIdx.x / CLN) * BPC;
  const int rg   = tid >> 4, kq = tid & 15;
  const float tauv = __ldg(&tau[0]), gamv = __ldg(&gam[0]);

  // -------- prologue: load this thread's weight fragments into registers --------
  // slot[m*4+r] = row (rank*64+rg*4+r), fp32 cols [kq*8+m*128, +8) as 8 bf16
  uint4 wC[16], wW[16];
  #pragma unroll
  for (int m=0;m<4;m++){
    #pragma unroll
    for (int r=0;r<4;r++){
      const float* srcC = &C1[(rank*64 + rg*4 + r)*HID + kq*8 + m*128];
      const float* srcW = &W1[(rank*64 + rg*4 + r)*HID + kq*8 + m*128];
      float4 c0 = __ldg((const float4*)srcC);
      float4 c1 = __ldg((const float4*)(srcC+4));
      float4 v0 = __ldg((const float4*)srcW);
      float4 v1 = __ldg((const float4*)(srcW+4));
      __nv_bfloat162 bc0 = __floats2bfloat162_rn(c0.x, c0.y);
      __nv_bfloat162 bc1 = __floats2bfloat162_rn(c0.z, c0.w);
      __nv_bfloat162 bc2 = __floats2bfloat162_rn(c1.x, c1.y);
      __nv_bfloat162 bc3 = __floats2bfloat162_rn(c1.z, c1.w);
      __nv_bfloat162 bw0 = __floats2bfloat162_rn(v0.x, v0.y);
      __nv_bfloat162 bw1 = __floats2bfloat162_rn(v0.z, v0.w);
      __nv_bfloat162 bw2 = __floats2bfloat162_rn(v1.x, v1.y);
      __nv_bfloat162 bw3 = __floats2bfloat162_rn(v1.z, v1.w);
      wC[m*4+r] = make_uint4(*(uint32_t*)&bc0, *(uint32_t*)&bc1,
                             *(uint32_t*)&bc2, *(uint32_t*)&bc3);
      wW[m*4+r] = make_uint4(*(uint32_t*)&bw0, *(uint32_t*)&bw1,
                             *(uint32_t*)&bw2, *(uint32_t*)&bw3);
    }
  }
  for (int i=tid;i<BPC*HID;i+=256) (&hbufP[0][0])[i]=0.f;
  if (tid<2*BPC) (&normloc[0][0])[tid]=0.f;
  if (tid<64)  sa[tid] = sigm(__ldg(&a1[rank*64+tid]));
  __syncthreads();

  const uint32_t a_ebuf = smem_u32(&ebufP[0][0]);
  const uint32_t a_hbuf = smem_u32(&hbufP[0][0]);
  const uint32_t a_narr = smem_u32(&narr[0][0]);

  const int eb = tid & 1, erow = tid >> 1;             // epilogue mapping (tid<128)
  const int dest = tid >> 5, chunk = tid & 31;         // push mapping (256 threads)
  const int pb = chunk >> 4, pq = chunk & 15;
  const uint32_t e_off = (uint32_t)(pb*HID + xpos(rank*16 + pq)*4)*4u;
  const int hk   = rank*64 + erow;
  const int hidx = eb*HID + xpos(hk>>2)*4 + (hk&3);

  // prefetch per-step scalars for t=0
  float xsv=1.f, be0v=0.f, be1v=0.f;
  if (tid<128){
    int bb = b0+eb;
    xsv  = __ldg(&g_xs1[bb*TT]);
    be0v = __ldg(&g_be0[(bb*TT)*HID + rank*64 + erow]);
  }

  for (int t=0;t<TT;t++){
    const int par = t&1;

    // ======== phase 1: p = h @ C1^T (own rows), err, norm partial ========
    {
      float acc[8];
      dot_reg(wC, (const uint8_t*)&hbufP[0][0], kq, acc);
      #pragma unroll
      for (int off=8; off; off>>=1)
        #pragma unroll
        for (int j=0;j<8;j++) acc[j] += __shfl_down_sync(0xffffffffu, acc[j], off);
      if (kq==0){
        #pragma unroll
        for (int j=0;j<4;j++) pout2[rg*4+j] = make_float2(acc[j*2], acc[j*2+1]);
      }
    }
    __syncthreads();
    if (tid<128){
      float pv = eb ? pout2[erow].y : pout2[erow].x;
      float p = tanhf(pv) * xsv;
      float e = be0v - p;
      estageP[eb][erow] = e;
      float q = e*e;
      #pragma unroll
      for (int off=16; off>=2; off>>=1) q += __shfl_xor_sync(0xffffffffu,q,off);
      if ((tid&31)<2) atomicAdd(&normloc[par][tid&1], q);
    }
    __syncthreads();
    {
      float4 v = ((const float4*)estageP)[chunk];
      dsmem_st4(a_ebuf + e_off, (uint32_t)dest, v);
      if (tid<16)
        dsmem_st1(a_narr + (uint32_t)(((tid&1)*CLN + rank)*4), (uint32_t)(tid>>1),
                  normloc[par][tid&1]);
    }
    CLUSTER_ARRIVE();
    if (tid<128)                    // be1 prefetch hides inside the barrier wait
      be1v = __ldg(&g_be1[((b0+eb)*TT+t)*HID + rank*64 + erow]);
    CLUSTER_WAIT();

    // ======== phase 2: surprise, ee = err @ W1^T, h update ========
    {
      float acc[8];
      dot_reg(wW, (const uint8_t*)&ebufP[0][0], kq, acc);
      #pragma unroll
      for (int off=8; off; off>>=1)
        #pragma unroll
        for (int j=0;j<8;j++) acc[j] += __shfl_down_sync(0xffffffffu, acc[j], off);
      if (kq==0){
        #pragma unroll
        for (int j=0;j<4;j++) pout2[rg*4+j] = make_float2(acc[j*2], acc[j*2+1]);
      }
    }
    __syncthreads();
    if (tid<128){
      float n2 = (narr[eb][0]+narr[eb][1])+(narr[eb][2]+narr[eb][3])
               + (narr[eb][4]+narr[eb][5])+(narr[eb][6]+narr[eb][7]);
      float rel = fminf(sqrtf(n2)/xsv, 4.0f);
      float s = sigm((rel - tauv)/gamv);
      float hold = (&hbufP[0][0])[hidx];
      float eev = eb ? pout2[erow].y : pout2[erow].x;
      float ih = 0.2f*hold + 0.6f*be1v + 0.2f*s*eev;
      float g = s*sa[erow];
      float hn = hold*(1.f-g) + tanhf(ih)*g;
      hstageP[eb][erow] = hn;
      g_h1[((b0+eb)*TT+t)*HID + rank*64 + erow] = hn;
      if (tid<2) normloc[par^1][tid] = 0.f;            // reset other slot
    }
    __syncthreads();
    {
      float4 v = ((const float4*)hstageP)[chunk];
      dsmem_st4(a_hbuf + e_off, (uint32_t)dest, v);
    }
    CLUSTER_ARRIVE();
    if (tid<128 && t+1<TT){         // next-step scalars hide inside the wait
      int bb = b0+eb;
      xsv  = __ldg(&g_xs1[bb*TT+t+1]);
      be0v = __ldg(&g_be0[(bb*TT+t+1)*HID + rank*64 + erow]);
    }
    CLUSTER_WAIT();
  }
}

// ---------------- head: out = [h1, be1] @ head_w^T + head_b ----------------
__global__ __launch_bounds__(256) void k_head(const float* __restrict__ hw,
                                              const float* __restrict__ hb,
                                              float* __restrict__ out){
  __shared__ float sh[8*1024];
  __shared__ float sred[4*8*64];
  int tid=threadIdx.x;
  int row0=blockIdx.x*8;
  for (int i=tid;i<8*1024;i+=256){
    int r=i>>10, j=i&1023;
    sh[i] = (j<512)? g_h1[(row0+r)*HID+j] : g_be1[(row0+r)*HID+(j-512)];
  }
  __syncthreads();
  int c=tid&63, q=tid>>6;
  float acc[8];
  #pragma unroll
  for (int r=0;r<8;r++) acc[r]=0.f;
  for (int k=q*256;k<q*256+256;k+=4){
    float4 w = *(const float4*)&hw[c*1024+k];
    #pragma unroll
    for (int r=0;r<8;r++){
      float4 x = *(const float4*)&sh[r*1024+k];
      acc[r] += w.x*x.x + w.y*x.y + w.z*x.z + w.w*x.w;
    }
  }
  #pragma unroll
  for (int r=0;r<8;r++) sred[(q*8+r)*64+c]=acc[r];
  __syncthreads();
  for (int i=tid;i<8*64;i+=256){
    int r=i>>6, cc=i&63;
    out[(row0+r)*NCLS+cc] = sred[r*64+cc] + sred[(8+r)*64+cc]
                          + sred[(16+r)*64+cc] + sred[(24+r)*64+cc] + __ldg(&hb[cc]);
  }
}

// ---------------- launch ----------------
extern "C" void kernel_launch(void* const* d_in, const int* in_sizes, int n_in,
                              void* d_out, int out_size){
  const float* feats=(const float*)d_in[0];
  const float* B0  =(const float*)d_in[2];
  const float* C1  =(const float*)d_in[7];
  const float* B1  =(const float*)d_in[8];
  const float* W1  =(const float*)d_in[9];
  const float* a1  =(const float*)d_in[10];
  const float* tau1=(const float*)d_in[11];
  const float* gam1=(const float*)d_in[12];
  const float* hw  =(const float*)d_in[13];
  const float* hb  =(const float*)d_in[14];
  float* out=(float*)d_out;

  k_be0   <<<NROW/16,256>>>(feats,B0);
  k_be1   <<<NROW/16,256>>>(B1);
  k_serial<<<NCTA,256>>>(C1,W1,a1,tau1,gam1);
  k_head  <<<NROW/8,256>>>(hw,hb,out);
}

// round 14
// speedup vs baseline: 1.4583x; 1.2776x over previous
#include <cuda_runtime.h>
#include <cuda_bf16.h>
#include <math.h>
#include <stdint.h>

#define BQ   16
#define TT   1000
#define MEL  80
#define HID  512
#define NCLS 64
#define NROW (BQ*TT)

#define CLN  8       // CTAs per cluster  (8 clusters x 8 CTAs = 64 -- proven placement)
#define NCTA 64
#define BPC  2       // batch elements per cluster

#define WROWB 1040u                 // bf16 row stride bytes (1024 + 16 pad)
#define WMATB (64u*WROWB)           // 66560 B per matrix slice
#define DYNSM (2u*WMATB)            // 133120 B

#define HROWS 32                    // k_head rows per block
#define HEAD_DYN (HROWS*1024*4)     // 131072 B

// ---------------- scratch (static device globals; no allocations) ----------------
__device__ float g_be0[NROW*HID];
__device__ float g_be1[NROW*HID];
__device__ float g_h1 [NROW*HID];
__device__ float g_xs1[NROW];

__device__ __forceinline__ float sigm(float x){ return 1.0f/(1.0f+expf(-x)); }

__device__ __forceinline__ uint32_t smem_u32(const void* p){
  uint32_t a;
  asm("{ .reg .u64 t; cvta.to.shared.u64 t, %1; cvt.u32.u64 %0, t; }" : "=r"(a) : "l"(p));
  return a;
}
__device__ __forceinline__ void dsmem_st4(uint32_t laddr, uint32_t rnk, float4 v){
  uint32_t ra;
  asm volatile("mapa.shared::cluster.u32 %0, %1, %2;" : "=r"(ra) : "r"(laddr), "r"(rnk));
  asm volatile("st.shared::cluster.v4.f32 [%0], {%1,%2,%3,%4};"
               :: "r"(ra), "f"(v.x), "f"(v.y), "f"(v.z), "f"(v.w) : "memory");
}
__device__ __forceinline__ void dsmem_st1(uint32_t laddr, uint32_t rnk, float v){
  uint32_t ra;
  asm volatile("mapa.shared::cluster.u32 %0, %1, %2;" : "=r"(ra) : "r"(laddr), "r"(rnk));
  asm volatile("st.shared::cluster.f32 [%0], %1;" :: "r"(ra), "f"(v) : "memory");
}
#define CLUSTER_ARRIVE() asm volatile("barrier.cluster.arrive.aligned;" ::: "memory")
#define CLUSTER_WAIT()   asm volatile("barrier.cluster.wait.aligned;"   ::: "memory")

// packed f32x2 FMA on NATIVE fp32 pairs (no bf16 unpack -> no pairing pressure)
__device__ __forceinline__ void ffma2(unsigned long long& a, unsigned long long w,
                                      unsigned long long x){
  asm("fma.rn.f32x2 %0, %1, %2, %0;" : "+l"(a) : "l"(w), "l"(x));
}
__device__ __forceinline__ float hsum2(unsigned long long a){
  return __uint_as_float((unsigned)(a & 0xffffffffu)) +
         __uint_as_float((unsigned)(a >> 32));
}

// permuted float4-group position for x buffers: group g (=k/4) -> pos
__host__ __device__ __forceinline__ int xpos(int g){
  int j = g>>1;
  return ((j>>4)<<5) + ((g&1)<<4) + (j&15);
}

// ---------------- be0 = clip(feats/||feats||) @ B0^T ; xs1 = ||be0|| ----------------
__global__ __launch_bounds__(256) void k_be0(const float* __restrict__ feats,
                                             const float* __restrict__ B0){
  __shared__ float xn[16][MEL];
  __shared__ float snorm[16];
  __shared__ float sxs[16];
  int tid = threadIdx.x;
  int row0 = blockIdx.x*16;
  for (int i=tid;i<16*MEL;i+=256)
    xn[i/MEL][i%MEL] = feats[row0*MEL + i];
  __syncthreads();
  if (tid<16){
    float s=0.f;
    #pragma unroll
    for (int k=0;k<MEL;k++){ float v=xn[tid][k]; s+=v*v; }
    sxs[tid]=fmaxf(sqrtf(s),1e-6f);
    snorm[tid]=0.f;
  }
  __syncthreads();
  for (int i=tid;i<16*MEL;i+=256){
    int r=i/MEL;
    float v = xn[r][i%MEL]/sxs[r];
    xn[r][i%MEL] = fminf(fmaxf(v,-1.f),1.f);
  }
  __syncthreads();
  int n0=tid, n1=tid+256;
  float a0[16], a1_[16];
  #pragma unroll
  for (int r=0;r<16;r++){ a0[r]=0.f; a1_[r]=0.f; }
  for (int k=0;k<MEL;k+=4){
    float4 w0 = *(const float4*)&B0[n0*MEL+k];
    float4 w1 = *(const float4*)&B0[n1*MEL+k];
    #pragma unroll
    for (int r=0;r<16;r++){
      float4 x = *(const float4*)&xn[r][k];
      a0 [r] += w0.x*x.x + w0.y*x.y + w0.z*x.z + w0.w*x.w;
      a1_[r] += w1.x*x.x + w1.y*x.y + w1.z*x.z + w1.w*x.w;
    }
  }
  #pragma unroll
  for (int r=0;r<16;r++){
    g_be0[(row0+r)*HID+n0]=a0[r];
    g_be0[(row0+r)*HID+n1]=a1_[r];
    atomicAdd(&snorm[r], a0[r]*a0[r] + a1_[r]*a1_[r]);
  }
  __syncthreads();
  if (tid<16) g_xs1[row0+tid] = fmaxf(sqrtf(snorm[tid]),1e-6f);
}

// ---------------- be1 = clip(be0/xs1) @ B1^T  (f32x2 packed FMA) ----------------
__global__ __launch_bounds__(256) void k_be1(const float* __restrict__ B1){
  __shared__ float xn[16][HID];
  __shared__ float sxs[16];
  int tid=threadIdx.x;
  int row0=blockIdx.x*16;
  if (tid<16) sxs[tid]=g_xs1[row0+tid];
  __syncthreads();
  for (int i=tid;i<16*HID;i+=256){
    int r=i>>9;
    float v = g_be0[row0*HID + i]/sxs[r];
    xn[r][i&511] = fminf(fmaxf(v,-1.f),1.f);
  }
  __syncthreads();
  int n0=tid, n1=tid+256;
  unsigned long long a0[16], a1_[16];
  #pragma unroll
  for (int r=0;r<16;r++){ a0[r]=0ull; a1_[r]=0ull; }
  for (int k=0;k<HID;k+=4){
    ulonglong2 w0 = *(const ulonglong2*)&B1[n0*HID+k];
    ulonglong2 w1 = *(const ulonglong2*)&B1[n1*HID+k];
    #pragma unroll
    for (int r=0;r<16;r++){
      ulonglong2 x = *(const ulonglong2*)&xn[r][k];
      ffma2(a0[r],  w0.x, x.x); ffma2(a0[r],  w0.y, x.y);
      ffma2(a1_[r], w1.x, x.x); ffma2(a1_[r], w1.y, x.y);
    }
  }
  #pragma unroll
  for (int r=0;r<16;r++){
    g_be1[(row0+r)*HID+n0]=hsum2(a0[r]);
    g_be1[(row0+r)*HID+n1]=hsum2(a1_[r]);
  }
}

// ---------------- serial recurrence (R9 EXACT -- proven 3931us) -------------------
__device__ __forceinline__ void dot_bf16(const uint8_t* __restrict__ wsm,
                                         const uint8_t* __restrict__ xb,
                                         int rg, int kq, float* __restrict__ acc){
  const uint8_t* wr = wsm + (unsigned)(rg*4)*WROWB + (unsigned)kq*16u;
  #pragma unroll
  for (int m=0;m<4;m++){
    float4 xa0 = *(const float4*)(xb + (m*32+kq)*16);
    float4 xa1 = *(const float4*)(xb + (m*32+16+kq)*16);
    float4 xb0 = *(const float4*)(xb + 2048 + (m*32+kq)*16);
    float4 xb1 = *(const float4*)(xb + 2048 + (m*32+16+kq)*16);
    #pragma unroll
    for (int r=0;r<4;r++){
      uint4 w = *(const uint4*)(wr + (unsigned)r*WROWB + (unsigned)m*256u);
      float w0=__uint_as_float(w.x<<16), w1=__uint_as_float(w.x&0xffff0000u);
      float w2=__uint_as_float(w.y<<16), w3=__uint_as_float(w.y&0xffff0000u);
      float w4=__uint_as_float(w.z<<16), w5=__uint_as_float(w.z&0xffff0000u);
      float w6=__uint_as_float(w.w<<16), w7=__uint_as_float(w.w&0xffff0000u);
      acc[r*2+0] += w0*xa0.x + w1*xa0.y + w2*xa0.z + w3*xa0.w
                  + w4*xa1.x + w5*xa1.y + w6*xa1.z + w7*xa1.w;
      acc[r*2+1] += w0*xb0.x + w1*xb0.y + w2*xb0.z + w3*xb0.w
                  + w4*xb1.x + w5*xb1.y + w6*xb1.z + w7*xb1.w;
    }
  }
}

__global__ __launch_bounds__(256,1) __cluster_dims__(CLN,1,1)
void k_serial(const float* __restrict__ C1, const float* __restrict__ W1,
              const float* __restrict__ a1, const float* __restrict__ tau,
              const float* __restrict__ gam){
  extern __shared__ __align__(16) uint8_t dynsm[];
  uint8_t* wsmC = dynsm;                 // [64][WROWB] bf16
  uint8_t* wsmW = dynsm + WMATB;

  __shared__ __align__(16) float hbufP[BPC][HID];    // permuted h   (remote-written)
  __shared__ __align__(16) float ebufP[BPC][HID];    // permuted err (remote-written)
  __shared__ __align__(16) float estageP[BPC][64];
  __shared__ __align__(16) float hstageP[BPC][64];
  __shared__ float2 pout2[64];
  __shared__ float narr[BPC][CLN];
  __shared__ float normloc[2][BPC];                  // ping-pong by step parity
  __shared__ float sa[64];

  const int tid  = threadIdx.x;
  const int rank = blockIdx.x & (CLN-1);
  const int b0   = (blockIdx.x / CLN) * BPC;
  const int rg   = tid >> 4, kq = tid & 15;
  const float tauv = __ldg(&tau[0]), gamv = __ldg(&gam[0]);

  for (int i=tid; i<64*128; i+=256){
    int r=i>>7, q=i&127;
    float4 vc = __ldg((const float4*)&C1[(rank*64+r)*HID + q*4]);
    float4 vw = __ldg((const float4*)&W1[(rank*64+r)*HID + q*4]);
    __nv_bfloat162 c0 = __floats2bfloat162_rn(vc.x, vc.y);
    __nv_bfloat162 c1 = __floats2bfloat162_rn(vc.z, vc.w);
    __nv_bfloat162 w0 = __floats2bfloat162_rn(vw.x, vw.y);
    __nv_bfloat162 w1 = __floats2bfloat162_rn(vw.z, vw.w);
    uint2 uc; uc.x = *(uint32_t*)&c0; uc.y = *(uint32_t*)&c1;
    uint2 uw; uw.x = *(uint32_t*)&w0; uw.y = *(uint32_t*)&w1;
    *(uint2*)(wsmC + (unsigned)r*WROWB + (unsigned)q*8u) = uc;
    *(uint2*)(wsmW + (unsigned)r*WROWB + (unsigned)q*8u) = uw;
  }
  for (int i=tid;i<BPC*HID;i+=256) (&hbufP[0][0])[i]=0.f;
  if (tid<2*BPC) (&normloc[0][0])[tid]=0.f;
  if (tid<64)  sa[tid] = sigm(__ldg(&a1[rank*64+tid]));
  __syncthreads();

  const uint32_t a_ebuf = smem_u32(&ebufP[0][0]);
  const uint32_t a_hbuf = smem_u32(&hbufP[0][0]);
  const uint32_t a_narr = smem_u32(&narr[0][0]);

  const int eb = tid & 1, erow = tid >> 1;             // epilogue mapping (tid<128)
  const int dest = tid >> 5, chunk = tid & 31;         // push mapping (256 threads)
  const int pb = chunk >> 4, pq = chunk & 15;
  const uint32_t e_off = (uint32_t)(pb*HID + xpos(rank*16 + pq)*4)*4u;
  const int hk   = rank*64 + erow;
  const int hidx = eb*HID + xpos(hk>>2)*4 + (hk&3);

  float xsv=1.f, be0v=0.f, be1v=0.f;
  if (tid<128){
    int bb = b0+eb;
    xsv  = __ldg(&g_xs1[bb*TT]);
    be0v = __ldg(&g_be0[(bb*TT)*HID + rank*64 + erow]);
  }

  for (int t=0;t<TT;t++){
    const int par = t&1;

    {
      float acc[8] = {0.f,0.f,0.f,0.f,0.f,0.f,0.f,0.f};
      dot_bf16(wsmC, (const uint8_t*)&hbufP[0][0], rg, kq, acc);
      #pragma unroll
      for (int off=8; off; off>>=1)
        #pragma unroll
        for (int j=0;j<8;j++) acc[j] += __shfl_down_sync(0xffffffffu, acc[j], off);
      if (kq==0){
        #pragma unroll
        for (int j=0;j<4;j++) pout2[rg*4+j] = make_float2(acc[j*2], acc[j*2+1]);
      }
    }
    __syncthreads();
    if (tid<128){
      float pv = eb ? pout2[erow].y : pout2[erow].x;
      float p = tanhf(pv) * xsv;
      float e = be0v - p;
      estageP[eb][erow] = e;
      float q = e*e;
      #pragma unroll
      for (int off=16; off>=2; off>>=1) q += __shfl_xor_sync(0xffffffffu,q,off);
      if ((tid&31)<2) atomicAdd(&normloc[par][tid&1], q);
    }
    __syncthreads();
    {
      float4 v = ((const float4*)estageP)[chunk];
      dsmem_st4(a_ebuf + e_off, (uint32_t)dest, v);
      if (tid<16)
        dsmem_st1(a_narr + (uint32_t)(((tid&1)*CLN + rank)*4), (uint32_t)(tid>>1),
                  normloc[par][tid&1]);
    }
    CLUSTER_ARRIVE();
    if (tid<128)
      be1v = __ldg(&g_be1[((b0+eb)*TT+t)*HID + rank*64 + erow]);
    CLUSTER_WAIT();

    {
      float acc[8] = {0.f,0.f,0.f,0.f,0.f,0.f,0.f,0.f};
      dot_bf16(wsmW, (const uint8_t*)&ebufP[0][0], rg, kq, acc);
      #pragma unroll
      for (int off=8; off; off>>=1)
        #pragma unroll
        for (int j=0;j<8;j++) acc[j] += __shfl_down_sync(0xffffffffu, acc[j], off);
      if (kq==0){
        #pragma unroll
        for (int j=0;j<4;j++) pout2[rg*4+j] = make_float2(acc[j*2], acc[j*2+1]);
      }
    }
    __syncthreads();
    if (tid<128){
      float n2 = (narr[eb][0]+narr[eb][1])+(narr[eb][2]+narr[eb][3])
               + (narr[eb][4]+narr[eb][5])+(narr[eb][6]+narr[eb][7]);
      float rel = fminf(sqrtf(n2)/xsv, 4.0f);
      float s = sigm((rel - tauv)/gamv);
      float hold = (&hbufP[0][0])[hidx];
      float eev = eb ? pout2[erow].y : pout2[erow].x;
      float ih = 0.2f*hold + 0.6f*be1v + 0.2f*s*eev;
      float g = s*sa[erow];
      float hn = hold*(1.f-g) + tanhf(ih)*g;
      hstageP[eb][erow] = hn;
      g_h1[((b0+eb)*TT+t)*HID + rank*64 + erow] = hn;
      if (tid<2) normloc[par^1][tid] = 0.f;
    }
    __syncthreads();
    {
      float4 v = ((const float4*)hstageP)[chunk];
      dsmem_st4(a_hbuf + e_off, (uint32_t)dest, v);
    }
    CLUSTER_ARRIVE();
    if (tid<128 && t+1<TT){
      int bb = b0+eb;
      xsv  = __ldg(&g_xs1[bb*TT+t+1]);
      be0v = __ldg(&g_be0[(bb*TT+t+1)*HID + rank*64 + erow]);
    }
    CLUSTER_WAIT();
  }
}

// ---------------- head: 32 rows/block, f32x2, x staged in dynamic smem ------------
__global__ __launch_bounds__(256) void k_head(const float* __restrict__ hw,
                                              const float* __restrict__ hb,
                                              float* __restrict__ out){
  extern __shared__ __align__(16) float sh[];        // [HROWS][1024]
  __shared__ float sred[4][HROWS][64];
  int tid=threadIdx.x;
  int row0=blockIdx.x*HROWS;
  for (int i=tid;i<HROWS*256;i+=256){                // float4 granularity
    int r=i>>8, j4=i&255;
    float4 v;
    if (j4<128) v = *(const float4*)&g_h1 [(row0+r)*HID + j4*4];
    else        v = *(const float4*)&g_be1[(row0+r)*HID + (j4-128)*4];
    ((float4*)sh)[i] = v;
  }
  __syncthreads();
  int c=tid&63, q=tid>>6;
  unsigned long long acc[HROWS];
  #pragma unroll
  for (int r=0;r<HROWS;r++) acc[r]=0ull;
  const float* wrow = &hw[c*1024 + q*256];
  for (int k4=0;k4<64;k4++){
    ulonglong2 wp = *(const ulonglong2*)(wrow + k4*4);
    #pragma unroll
    for (int r=0;r<HROWS;r++){
      ulonglong2 xp = *(const ulonglong2*)&sh[r*1024 + q*256 + k4*4];
      ffma2(acc[r], wp.x, xp.x); ffma2(acc[r], wp.y, xp.y);
    }
  }
  #pragma unroll
  for (int r=0;r<HROWS;r++) sred[q][r][c]=hsum2(acc[r]);
  __syncthreads();
  for (int i=tid;i<HROWS*64;i+=256){
    int r=i>>6, cc=i&63;
    out[(row0+r)*NCLS+cc] = sred[0][r][cc]+sred[1][r][cc]
                          + sred[2][r][cc]+sred[3][r][cc] + __ldg(&hb[cc]);
  }
}

// ---------------- launch ----------------
extern "C" void kernel_launch(void* const* d_in, const int* in_sizes, int n_in,
                              void* d_out, int out_size){
  const float* feats=(const float*)d_in[0];
  const float* B0  =(const float*)d_in[2];
  const float* C1  =(const float*)d_in[7];
  const float* B1  =(const float*)d_in[8];
  const float* W1  =(const float*)d_in[9];
  const float* a1  =(const float*)d_in[10];
  const float* tau1=(const float*)d_in[11];
  const float* gam1=(const float*)d_in[12];
  const float* hw  =(const float*)d_in[13];
  const float* hb  =(const float*)d_in[14];
  float* out=(float*)d_out;

  static int smem_set = 0;
  if (!smem_set){
    cudaFuncSetAttribute(k_serial, cudaFuncAttributeMaxDynamicSharedMemorySize, DYNSM);
    cudaFuncSetAttribute(k_head,   cudaFuncAttributeMaxDynamicSharedMemorySize, HEAD_DYN);
    smem_set = 1;
  }

  k_be0   <<<NROW/16,256>>>(feats,B0);
  k_be1   <<<NROW/16,256>>>(B1);
  k_serial<<<NCTA,256,DYNSM>>>(C1,W1,a1,tau1,gam1);
  k_head  <<<NROW/HROWS,256,HEAD_DYN>>>(hw,hb,out);
}

// round 15
// speedup vs baseline: 1.4626x; 1.0030x over previous
#include <cuda_runtime.h>
#include <cuda_bf16.h>
#include <math.h>
#include <stdint.h>

#define BQ   16
#define TT   1000
#define MEL  80
#define HID  512
#define NCLS 64
#define NROW (BQ*TT)

#define CLN  8       // CTAs per cluster  (8 clusters x 8 CTAs = 64 -- proven placement)
#define NCTA 64
#define BPC  2       // batch elements per cluster

#define WROWB 1040u                 // bf16 row stride bytes (1024 + 16 pad)
#define WMATB (64u*WROWB)           // 66560 B per matrix slice
#define DYNSM (2u*WMATB)            // 133120 B

#define HROWS 32                    // k_head rows per block
#define HEAD_DYN (HROWS*1024*4)     // 131072 B

// ---------------- scratch (static device globals; no allocations) ----------------
__device__ float g_be0[NROW*HID];
__device__ float g_be1[NROW*HID];
__device__ float g_h1 [NROW*HID];
__device__ float g_xs1[NROW];

__device__ __forceinline__ float sigm(float x){ return 1.0f/(1.0f+expf(-x)); }

__device__ __forceinline__ uint32_t smem_u32(const void* p){
  uint32_t a;
  asm("{ .reg .u64 t; cvta.to.shared.u64 t, %1; cvt.u32.u64 %0, t; }" : "=r"(a) : "l"(p));
  return a;
}
__device__ __forceinline__ void dsmem_st4(uint32_t laddr, uint32_t rnk, float4 v){
  uint32_t ra;
  asm volatile("mapa.shared::cluster.u32 %0, %1, %2;" : "=r"(ra) : "r"(laddr), "r"(rnk));
  asm volatile("st.shared::cluster.v4.f32 [%0], {%1,%2,%3,%4};"
               :: "r"(ra), "f"(v.x), "f"(v.y), "f"(v.z), "f"(v.w) : "memory");
}
__device__ __forceinline__ void dsmem_st1(uint32_t laddr, uint32_t rnk, float v){
  uint32_t ra;
  asm volatile("mapa.shared::cluster.u32 %0, %1, %2;" : "=r"(ra) : "r"(laddr), "r"(rnk));
  asm volatile("st.shared::cluster.f32 [%0], %1;" :: "r"(ra), "f"(v) : "memory");
}
#define CLUSTER_ARRIVE() asm volatile("barrier.cluster.arrive.aligned;" ::: "memory")
#define CLUSTER_WAIT()   asm volatile("barrier.cluster.wait.aligned;"   ::: "memory")

// packed f32x2 FMA helpers
__device__ __forceinline__ void ffma2(unsigned long long& a, unsigned long long w,
                                      unsigned long long x){
  asm("fma.rn.f32x2 %0, %1, %2, %0;" : "+l"(a) : "l"(w), "l"(x));
}
__device__ __forceinline__ float hsum2(unsigned long long a){
  return __uint_as_float((unsigned)(a & 0xffffffffu)) +
         __uint_as_float((unsigned)(a >> 32));
}
// unpack a bf16x2 word into an f32x2 pair (transient; ptxas can pair-allocate)
__device__ __forceinline__ unsigned long long bf2pair(uint32_t w){
  unsigned long long p;
  asm("{ .reg .b32 lo,hi;\n\t"
      "shl.b32 lo, %1, 16;\n\t"
      "and.b32 hi, %1, 0xffff0000;\n\t"
      "mov.b64 %0, {lo,hi}; }"
      : "=l"(p) : "r"(w));
  return p;
}

// permuted float4-group position for x buffers: group g (=k/4) -> pos
__host__ __device__ __forceinline__ int xpos(int g){
  int j = g>>1;
  return ((j>>4)<<5) + ((g&1)<<4) + (j&15);
}

// ---------------- be0 = clip(feats/||feats||) @ B0^T ; xs1 = ||be0|| ----------------
__global__ __launch_bounds__(256) void k_be0(const float* __restrict__ feats,
                                             const float* __restrict__ B0){
  __shared__ float xn[16][MEL];
  __shared__ float snorm[16];
  __shared__ float sxs[16];
  int tid = threadIdx.x;
  int row0 = blockIdx.x*16;
  for (int i=tid;i<16*MEL;i+=256)
    xn[i/MEL][i%MEL] = feats[row0*MEL + i];
  __syncthreads();
  if (tid<16){
    float s=0.f;
    #pragma unroll
    for (int k=0;k<MEL;k++){ float v=xn[tid][k]; s+=v*v; }
    sxs[tid]=fmaxf(sqrtf(s),1e-6f);
    snorm[tid]=0.f;
  }
  __syncthreads();
  for (int i=tid;i<16*MEL;i+=256){
    int r=i/MEL;
    float v = xn[r][i%MEL]/sxs[r];
    xn[r][i%MEL] = fminf(fmaxf(v,-1.f),1.f);
  }
  __syncthreads();
  int n0=tid, n1=tid+256;
  float a0[16], a1_[16];
  #pragma unroll
  for (int r=0;r<16;r++){ a0[r]=0.f; a1_[r]=0.f; }
  for (int k=0;k<MEL;k+=4){
    float4 w0 = *(const float4*)&B0[n0*MEL+k];
    float4 w1 = *(const float4*)&B0[n1*MEL+k];
    #pragma unroll
    for (int r=0;r<16;r++){
      float4 x = *(const float4*)&xn[r][k];
      a0 [r] += w0.x*x.x + w0.y*x.y + w0.z*x.z + w0.w*x.w;
      a1_[r] += w1.x*x.x + w1.y*x.y + w1.z*x.z + w1.w*x.w;
    }
  }
  #pragma unroll
  for (int r=0;r<16;r++){
    g_be0[(row0+r)*HID+n0]=a0[r];
    g_be0[(row0+r)*HID+n1]=a1_[r];
    atomicAdd(&snorm[r], a0[r]*a0[r] + a1_[r]*a1_[r]);
  }
  __syncthreads();
  if (tid<16) g_xs1[row0+tid] = fmaxf(sqrtf(snorm[tid]),1e-6f);
}

// ---------------- be1 = clip(be0/xs1) @ B1^T  (f32x2 packed FMA) ----------------
__global__ __launch_bounds__(256) void k_be1(const float* __restrict__ B1){
  __shared__ float xn[16][HID];
  __shared__ float sxs[16];
  int tid=threadIdx.x;
  int row0=blockIdx.x*16;
  if (tid<16) sxs[tid]=g_xs1[row0+tid];
  __syncthreads();
  for (int i=tid;i<16*HID;i+=256){
    int r=i>>9;
    float v = g_be0[row0*HID + i]/sxs[r];
    xn[r][i&511] = fminf(fmaxf(v,-1.f),1.f);
  }
  __syncthreads();
  int n0=tid, n1=tid+256;
  unsigned long long a0[16], a1_[16];
  #pragma unroll
  for (int r=0;r<16;r++){ a0[r]=0ull; a1_[r]=0ull; }
  for (int k=0;k<HID;k+=4){
    ulonglong2 w0 = *(const ulonglong2*)&B1[n0*HID+k];
    ulonglong2 w1 = *(const ulonglong2*)&B1[n1*HID+k];
    #pragma unroll
    for (int r=0;r<16;r++){
      ulonglong2 x = *(const ulonglong2*)&xn[r][k];
      ffma2(a0[r],  w0.x, x.x); ffma2(a0[r],  w0.y, x.y);
      ffma2(a1_[r], w1.x, x.x); ffma2(a1_[r], w1.y, x.y);
    }
  }
  #pragma unroll
  for (int r=0;r<16;r++){
    g_be1[(row0+r)*HID+n0]=hsum2(a0[r]);
    g_be1[(row0+r)*HID+n1]=hsum2(a1_[r]);
  }
}

// ---------------- serial recurrence (R9 skeleton; dot in f32x2) -------------------
// CTA `rank` owns rows [rank*64,+64). Weights bf16 in smem; x vectors exchanged by
// DSMEM push (permuted conflict-free layout); split cluster barriers with prefetch
// in the wait windows. Dot: same LDS layout/broadcast as R9, but k paired into
// fma.rn.f32x2 (FFMA instrs halved; weight pairs are transient asm-built values).
__device__ __forceinline__ void dot_bf16(const uint8_t* __restrict__ wsm,
                                         const uint8_t* __restrict__ xb,
                                         int rg, int kq, float* __restrict__ acc){
  const uint8_t* wr = wsm + (unsigned)(rg*4)*WROWB + (unsigned)kq*16u;
  unsigned long long aA[4]={0ull,0ull,0ull,0ull}, aB[4]={0ull,0ull,0ull,0ull};
  #pragma unroll
  for (int m=0;m<4;m++){
    ulonglong2 xa0 = *(const ulonglong2*)(xb + (m*32+kq)*16);
    ulonglong2 xa1 = *(const ulonglong2*)(xb + (m*32+16+kq)*16);
    ulonglong2 xb0 = *(const ulonglong2*)(xb + 2048 + (m*32+kq)*16);
    ulonglong2 xb1 = *(const ulonglong2*)(xb + 2048 + (m*32+16+kq)*16);
    #pragma unroll
    for (int r=0;r<4;r++){
      uint4 w = *(const uint4*)(wr + (unsigned)r*WROWB + (unsigned)m*256u);
      unsigned long long p0 = bf2pair(w.x);
      unsigned long long p1 = bf2pair(w.y);
      unsigned long long p2 = bf2pair(w.z);
      unsigned long long p3 = bf2pair(w.w);
      ffma2(aA[r], p0, xa0.x); ffma2(aA[r], p1, xa0.y);
      ffma2(aA[r], p2, xa1.x); ffma2(aA[r], p3, xa1.y);
      ffma2(aB[r], p0, xb0.x); ffma2(aB[r], p1, xb0.y);
      ffma2(aB[r], p2, xb1.x); ffma2(aB[r], p3, xb1.y);
    }
  }
  #pragma unroll
  for (int r=0;r<4;r++){ acc[r*2]=hsum2(aA[r]); acc[r*2+1]=hsum2(aB[r]); }
}

__global__ __launch_bounds__(256,1) __cluster_dims__(CLN,1,1)
void k_serial(const float* __restrict__ C1, const float* __restrict__ W1,
              const float* __restrict__ a1, const float* __restrict__ tau,
              const float* __restrict__ gam){
  extern __shared__ __align__(16) uint8_t dynsm[];
  uint8_t* wsmC = dynsm;                 // [64][WROWB] bf16
  uint8_t* wsmW = dynsm + WMATB;

  __shared__ __align__(16) float hbufP[BPC][HID];    // permuted h   (remote-written)
  __shared__ __align__(16) float ebufP[BPC][HID];    // permuted err (remote-written)
  __shared__ __align__(16) float estageP[BPC][64];
  __shared__ __align__(16) float hstageP[BPC][64];
  __shared__ float2 pout2[64];
  __shared__ float narr[BPC][CLN];
  __shared__ float normloc[2][BPC];                  // ping-pong by step parity
  __shared__ float sa[64];

  const int tid  = threadIdx.x;
  const int rank = blockIdx.x & (CLN-1);
  const int b0   = (blockIdx.x / CLN) * BPC;
  const int rg   = tid >> 4, kq = tid & 15;
  const float tauv = __ldg(&tau[0]), gamv = __ldg(&gam[0]);

  for (int i=tid; i<64*128; i+=256){
    int r=i>>7, q=i&127;
    float4 vc = __ldg((const float4*)&C1[(rank*64+r)*HID + q*4]);
    float4 vw = __ldg((const float4*)&W1[(rank*64+r)*HID + q*4]);
    __nv_bfloat162 c0 = __floats2bfloat162_rn(vc.x, vc.y);
    __nv_bfloat162 c1 = __floats2bfloat162_rn(vc.z, vc.w);
    __nv_bfloat162 w0 = __floats2bfloat162_rn(vw.x, vw.y);
    __nv_bfloat162 w1 = __floats2bfloat162_rn(vw.z, vw.w);
    uint2 uc; uc.x = *(uint32_t*)&c0; uc.y = *(uint32_t*)&c1;
    uint2 uw; uw.x = *(uint32_t*)&w0; uw.y = *(uint32_t*)&w1;
    *(uint2*)(wsmC + (unsigned)r*WROWB + (unsigned)q*8u) = uc;
    *(uint2*)(wsmW + (unsigned)r*WROWB + (unsigned)q*8u) = uw;
  }
  for (int i=tid;i<BPC*HID;i+=256) (&hbufP[0][0])[i]=0.f;
  if (tid<2*BPC) (&normloc[0][0])[tid]=0.f;
  if (tid<64)  sa[tid] = sigm(__ldg(&a1[rank*64+tid]));
  __syncthreads();

  const uint32_t a_ebuf = smem_u32(&ebufP[0][0]);
  const uint32_t a_hbuf = smem_u32(&hbufP[0][0]);
  const uint32_t a_narr = smem_u32(&narr[0][0]);

  const int eb = tid & 1, erow = tid >> 1;             // epilogue mapping (tid<128)
  const int dest = tid >> 5, chunk = tid & 31;         // push mapping (256 threads)
  const int pb = chunk >> 4, pq = chunk & 15;
  const uint32_t e_off = (uint32_t)(pb*HID + xpos(rank*16 + pq)*4)*4u;
  const int hk   = rank*64 + erow;
  const int hidx = eb*HID + xpos(hk>>2)*4 + (hk&3);

  float xsv=1.f, be0v=0.f, be1v=0.f;
  if (tid<128){
    int bb = b0+eb;
    xsv  = __ldg(&g_xs1[bb*TT]);
    be0v = __ldg(&g_be0[(bb*TT)*HID + rank*64 + erow]);
  }

  for (int t=0;t<TT;t++){
    const int par = t&1;

    {
      float acc[8];
      dot_bf16(wsmC, (const uint8_t*)&hbufP[0][0], rg, kq, acc);
      #pragma unroll
      for (int off=8; off; off>>=1)
        #pragma unroll
        for (int j=0;j<8;j++) acc[j] += __shfl_down_sync(0xffffffffu, acc[j], off);
      if (kq==0){
        #pragma unroll
        for (int j=0;j<4;j++) pout2[rg*4+j] = make_float2(acc[j*2], acc[j*2+1]);
      }
    }
    __syncthreads();
    if (tid<128){
      float pv = eb ? pout2[erow].y : pout2[erow].x;
      float p = tanhf(pv) * xsv;
      float e = be0v - p;
      estageP[eb][erow] = e;
      float q = e*e;
      #pragma unroll
      for (int off=16; off>=2; off>>=1) q += __shfl_xor_sync(0xffffffffu,q,off);
      if ((tid&31)<2) atomicAdd(&normloc[par][tid&1], q);
    }
    __syncthreads();
    {
      float4 v = ((const float4*)estageP)[chunk];
      dsmem_st4(a_ebuf + e_off, (uint32_t)dest, v);
      if (tid<16)
        dsmem_st1(a_narr + (uint32_t)(((tid&1)*CLN + rank)*4), (uint32_t)(tid>>1),
                  normloc[par][tid&1]);
    }
    CLUSTER_ARRIVE();
    if (tid<128)
      be1v = __ldg(&g_be1[((b0+eb)*TT+t)*HID + rank*64 + erow]);
    CLUSTER_WAIT();

    {
      float acc[8];
      dot_bf16(wsmW, (const uint8_t*)&ebufP[0][0], rg, kq, acc);
      #pragma unroll
      for (int off=8; off; off>>=1)
        #pragma unroll
        for (int j=0;j<8;j++) acc[j] += __shfl_down_sync(0xffffffffu, acc[j], off);
      if (kq==0){
        #pragma unroll
        for (int j=0;j<4;j++) pout2[rg*4+j] = make_float2(acc[j*2], acc[j*2+1]);
      }
    }
    __syncthreads();
    if (tid<128){
      float n2 = (narr[eb][0]+narr[eb][1])+(narr[eb][2]+narr[eb][3])
               + (narr[eb][4]+narr[eb][5])+(narr[eb][6]+narr[eb][7]);
      float rel = fminf(sqrtf(n2)/xsv, 4.0f);
      float s = sigm((rel - tauv)/gamv);
      float hold = (&hbufP[0][0])[hidx];
      float eev = eb ? pout2[erow].y : pout2[erow].x;
      float ih = 0.2f*hold + 0.6f*be1v + 0.2f*s*eev;
      float g = s*sa[erow];
      float hn = hold*(1.f-g) + tanhf(ih)*g;
      hstageP[eb][erow] = hn;
      g_h1[((b0+eb)*TT+t)*HID + rank*64 + erow] = hn;
      if (tid<2) normloc[par^1][tid] = 0.f;
    }
    __syncthreads();
    {
      float4 v = ((const float4*)hstageP)[chunk];
      dsmem_st4(a_hbuf + e_off, (uint32_t)dest, v);
    }
    CLUSTER_ARRIVE();
    if (tid<128 && t+1<TT){
      int bb = b0+eb;
      xsv  = __ldg(&g_xs1[bb*TT+t+1]);
      be0v = __ldg(&g_be0[(bb*TT+t+1)*HID + rank*64 + erow]);
    }
    CLUSTER_WAIT();
  }
}

// ---------------- head: 32 rows/block, f32x2, x staged in dynamic smem ------------
__global__ __launch_bounds__(256) void k_head(const float* __restrict__ hw,
                                              const float* __restrict__ hb,
                                              float* __restrict__ out){
  extern __shared__ __align__(16) float sh[];        // [HROWS][1024]
  __shared__ float sred[4][HROWS][64];
  int tid=threadIdx.x;
  int row0=blockIdx.x*HROWS;
  for (int i=tid;i<HROWS*256;i+=256){                // float4 granularity
    int r=i>>8, j4=i&255;
    float4 v;
    if (j4<128) v = *(const float4*)&g_h1 [(row0+r)*HID + j4*4];
    else        v = *(const float4*)&g_be1[(row0+r)*HID + (j4-128)*4];
    ((float4*)sh)[i] = v;
  }
  __syncthreads();
  int c=tid&63, q=tid>>6;
  unsigned long long acc[HROWS];
  #pragma unroll
  for (int r=0;r<HROWS;r++) acc[r]=0ull;
  const float* wrow = &hw[c*1024 + q*256];
  for (int k4=0;k4<64;k4++){
    ulonglong2 wp = *(const ulonglong2*)(wrow + k4*4);
    #pragma unroll
    for (int r=0;r<HROWS;r++){
      ulonglong2 xp = *(const ulonglong2*)&sh[r*1024 + q*256 + k4*4];
      ffma2(acc[r], wp.x, xp.x); ffma2(acc[r], wp.y, xp.y);
    }
  }
  #pragma unroll
  for (int r=0;r<HROWS;r++) sred[q][r][c]=hsum2(acc[r]);
  __syncthreads();
  for (int i=tid;i<HROWS*64;i+=256){
    int r=i>>6, cc=i&63;
    out[(row0+r)*NCLS+cc] = sred[0][r][cc]+sred[1][r][cc]
                          + sred[2][r][cc]+sred[3][r][cc] + __ldg(&hb[cc]);
  }
}

// ---------------- launch ----------------
extern "C" void kernel_launch(void* const* d_in, const int* in_sizes, int n_in,
                              void* d_out, int out_size){
  const float* feats=(const float*)d_in[0];
  const float* B0  =(const float*)d_in[2];
  const float* C1  =(const float*)d_in[7];
  const float* B1  =(const float*)d_in[8];
  const float* W1  =(const float*)d_in[9];
  const float* a1  =(const float*)d_in[10];
  const float* tau1=(const float*)d_in[11];
  const float* gam1=(const float*)d_in[12];
  const float* hw  =(const float*)d_in[13];
  const float* hb  =(const float*)d_in[14];
  float* out=(float*)d_out;

  static int smem_set = 0;
  if (!smem_set){
    cudaFuncSetAttribute(k_serial, cudaFuncAttributeMaxDynamicSharedMemorySize, DYNSM);
    cudaFuncSetAttribute(k_head,   cudaFuncAttributeMaxDynamicSharedMemorySize, HEAD_DYN);
    smem_set = 1;
  }

  k_be0   <<<NROW/16,256>>>(feats,B0);
  k_be1   <<<NROW/16,256>>>(B1);
  k_serial<<<NCTA,256,DYNSM>>>(C1,W1,a1,tau1,gam1);
  k_head  <<<NROW/HROWS,256,HEAD_DYN>>>(hw,hb,out);
}

// round 16
// speedup vs baseline: 1.4977x; 1.0240x over previous
#include <cuda_runtime.h>
#include <cuda_bf16.h>
#include <math.h>
#include <stdint.h>

#define BQ   16
#define TT   1000
#define MEL  80
#define HID  512
#define NCLS 64
#define NROW (BQ*TT)

#define CLN  8       // CTAs per cluster  (8 clusters x 8 CTAs = 64 -- proven placement)
#define NCTA 64
#define BPC  2       // batch elements per cluster

#define WROWB 1040u                 // bf16 row stride bytes (1024 + 16 pad)
#define WMATB (64u*WROWB)           // 66560 B per matrix slice
#define DYNSM (2u*WMATB)            // 133120 B

#define HROWS 32                    // k_head rows per block
#define HEAD_DYN (HROWS*1024*4)     // 131072 B

// ---------------- scratch (static device globals; no allocations) ----------------
__device__ float g_be0[NROW*HID];
__device__ float g_be1[NROW*HID];
__device__ float g_h1 [NROW*HID];
__device__ float g_xs1[NROW];

__device__ __forceinline__ float sigm(float x){ return 1.0f/(1.0f+expf(-x)); }

__device__ __forceinline__ uint32_t smem_u32(const void* p){
  uint32_t a;
  asm("{ .reg .u64 t; cvta.to.shared.u64 t, %1; cvt.u32.u64 %0, t; }" : "=r"(a) : "l"(p));
  return a;
}
__device__ __forceinline__ void dsmem_st4(uint32_t laddr, uint32_t rnk, float4 v){
  uint32_t ra;
  asm volatile("mapa.shared::cluster.u32 %0, %1, %2;" : "=r"(ra) : "r"(laddr), "r"(rnk));
  asm volatile("st.shared::cluster.v4.f32 [%0], {%1,%2,%3,%4};"
               :: "r"(ra), "f"(v.x), "f"(v.y), "f"(v.z), "f"(v.w) : "memory");
}
__device__ __forceinline__ void dsmem_st1(uint32_t laddr, uint32_t rnk, float v){
  uint32_t ra;
  asm volatile("mapa.shared::cluster.u32 %0, %1, %2;" : "=r"(ra) : "r"(laddr), "r"(rnk));
  asm volatile("st.shared::cluster.f32 [%0], %1;" :: "r"(ra), "f"(v) : "memory");
}
#define CLUSTER_ARRIVE() asm volatile("barrier.cluster.arrive.aligned;" ::: "memory")
#define CLUSTER_WAIT()   asm volatile("barrier.cluster.wait.aligned;"   ::: "memory")

// packed f32x2 FMA helpers
__device__ __forceinline__ void ffma2(unsigned long long& a, unsigned long long w,
                                      unsigned long long x){
  asm("fma.rn.f32x2 %0, %1, %2, %0;" : "+l"(a) : "l"(w), "l"(x));
}
__device__ __forceinline__ float hsum2(unsigned long long a){
  return __uint_as_float((unsigned)(a & 0xffffffffu)) +
         __uint_as_float((unsigned)(a >> 32));
}
// unpack a bf16x2 word into an f32x2 pair (transient; ptxas can pair-allocate)
__device__ __forceinline__ unsigned long long bf2pair(uint32_t w){
  unsigned long long p;
  asm("{ .reg .b32 lo,hi;\n\t"
      "shl.b32 lo, %1, 16;\n\t"
      "and.b32 hi, %1, 0xffff0000;\n\t"
      "mov.b64 %0, {lo,hi}; }"
      : "=l"(p) : "r"(w));
  return p;
}

// permuted float4-group position for x buffers: group g (=k/4) -> pos
__host__ __device__ __forceinline__ int xpos(int g){
  int j = g>>1;
  return ((j>>4)<<5) + ((g&1)<<4) + (j&15);
}

// ---------------- be0 = clip(feats/||feats||) @ B0^T ; xs1 = ||be0|| ----------------
__global__ __launch_bounds__(256) void k_be0(const float* __restrict__ feats,
                                             const float* __restrict__ B0){
  __shared__ float xn[16][MEL];
  __shared__ float snorm[16];
  __shared__ float sxs[16];
  int tid = threadIdx.x;
  int row0 = blockIdx.x*16;
  for (int i=tid;i<16*MEL;i+=256)
    xn[i/MEL][i%MEL] = feats[row0*MEL + i];
  __syncthreads();
  if (tid<16){
    float s=0.f;
    #pragma unroll
    for (int k=0;k<MEL;k++){ float v=xn[tid][k]; s+=v*v; }
    sxs[tid]=fmaxf(sqrtf(s),1e-6f);
    snorm[tid]=0.f;
  }
  __syncthreads();
  for (int i=tid;i<16*MEL;i+=256){
    int r=i/MEL;
    float v = xn[r][i%MEL]/sxs[r];
    xn[r][i%MEL] = fminf(fmaxf(v,-1.f),1.f);
  }
  __syncthreads();
  int n0=tid, n1=tid+256;
  float a0[16], a1_[16];
  #pragma unroll
  for (int r=0;r<16;r++){ a0[r]=0.f; a1_[r]=0.f; }
  for (int k=0;k<MEL;k+=4){
    float4 w0 = *(const float4*)&B0[n0*MEL+k];
    float4 w1 = *(const float4*)&B0[n1*MEL+k];
    #pragma unroll
    for (int r=0;r<16;r++){
      float4 x = *(const float4*)&xn[r][k];
      a0 [r] += w0.x*x.x + w0.y*x.y + w0.z*x.z + w0.w*x.w;
      a1_[r] += w1.x*x.x + w1.y*x.y + w1.z*x.z + w1.w*x.w;
    }
  }
  #pragma unroll
  for (int r=0;r<16;r++){
    g_be0[(row0+r)*HID+n0]=a0[r];
    g_be0[(row0+r)*HID+n1]=a1_[r];
    atomicAdd(&snorm[r], a0[r]*a0[r] + a1_[r]*a1_[r]);
  }
  __syncthreads();
  if (tid<16) g_xs1[row0+tid] = fmaxf(sqrtf(snorm[tid]),1e-6f);
}

// ---------------- be1 = clip(be0/xs1) @ B1^T  (R9 scalar fp32 -- reverted) --------
__global__ __launch_bounds__(256) void k_be1(const float* __restrict__ B1){
  __shared__ float xn[16][HID];
  __shared__ float sxs[16];
  int tid=threadIdx.x;
  int row0=blockIdx.x*16;
  if (tid<16) sxs[tid]=g_xs1[row0+tid];
  __syncthreads();
  for (int i=tid;i<16*HID;i+=256){
    int r=i>>9;
    float v = g_be0[row0*HID + i]/sxs[r];
    xn[r][i&511] = fminf(fmaxf(v,-1.f),1.f);
  }
  __syncthreads();
  int n0=tid, n1=tid+256;
  float a0[16], a1_[16];
  #pragma unroll
  for (int r=0;r<16;r++){ a0[r]=0.f; a1_[r]=0.f; }
  for (int k=0;k<HID;k+=4){
    float4 w0 = *(const float4*)&B1[n0*HID+k];
    float4 w1 = *(const float4*)&B1[n1*HID+k];
    #pragma unroll
    for (int r=0;r<16;r++){
      float4 x = *(const float4*)&xn[r][k];
      a0 [r] += w0.x*x.x + w0.y*x.y + w0.z*x.z + w0.w*x.w;
      a1_[r] += w1.x*x.x + w1.y*x.y + w1.z*x.z + w1.w*x.w;
    }
  }
  #pragma unroll
  for (int r=0;r<16;r++){
    g_be1[(row0+r)*HID+n0]=a0[r];
    g_be1[(row0+r)*HID+n1]=a1_[r];
  }
}

// ---------------- serial recurrence (R9 skeleton; dot in f32x2, R14) --------------
__device__ __forceinline__ void dot_bf16(const uint8_t* __restrict__ wsm,
                                         const uint8_t* __restrict__ xb,
                                         int rg, int kq, float* __restrict__ acc){
  const uint8_t* wr = wsm + (unsigned)(rg*4)*WROWB + (unsigned)kq*16u;
  unsigned long long aA[4]={0ull,0ull,0ull,0ull}, aB[4]={0ull,0ull,0ull,0ull};
  #pragma unroll
  for (int m=0;m<4;m++){
    ulonglong2 xa0 = *(const ulonglong2*)(xb + (m*32+kq)*16);
    ulonglong2 xa1 = *(const ulonglong2*)(xb + (m*32+16+kq)*16);
    ulonglong2 xb0 = *(const ulonglong2*)(xb + 2048 + (m*32+kq)*16);
    ulonglong2 xb1 = *(const ulonglong2*)(xb + 2048 + (m*32+16+kq)*16);
    #pragma unroll
    for (int r=0;r<4;r++){
      uint4 w = *(const uint4*)(wr + (unsigned)r*WROWB + (unsigned)m*256u);
      unsigned long long p0 = bf2pair(w.x);
      unsigned long long p1 = bf2pair(w.y);
      unsigned long long p2 = bf2pair(w.z);
      unsigned long long p3 = bf2pair(w.w);
      ffma2(aA[r], p0, xa0.x); ffma2(aA[r], p1, xa0.y);
      ffma2(aA[r], p2, xa1.x); ffma2(aA[r], p3, xa1.y);
      ffma2(aB[r], p0, xb0.x); ffma2(aB[r], p1, xb0.y);
      ffma2(aB[r], p2, xb1.x); ffma2(aB[r], p3, xb1.y);
    }
  }
  #pragma unroll
  for (int r=0;r<4;r++){ acc[r*2]=hsum2(aA[r]); acc[r*2+1]=hsum2(aB[r]); }
}

__global__ __launch_bounds__(256,1) __cluster_dims__(CLN,1,1)
void k_serial(const float* __restrict__ C1, const float* __restrict__ W1,
              const float* __restrict__ a1, const float* __restrict__ tau,
              const float* __restrict__ gam){
  extern __shared__ __align__(16) uint8_t dynsm[];
  uint8_t* wsmC = dynsm;                 // [64][WROWB] bf16
  uint8_t* wsmW = dynsm + WMATB;

  __shared__ __align__(16) float hbufP[BPC][HID];    // permuted h   (remote-written)
  __shared__ __align__(16) float ebufP[BPC][HID];    // permuted err (remote-written)
  __shared__ __align__(16) float estageP[BPC][64];
  __shared__ __align__(16) float hstageP[BPC][64];
  __shared__ float2 pout2[64];
  __shared__ float narr[BPC][CLN];
  __shared__ float normloc[2][BPC];                  // ping-pong by step parity
  __shared__ float sa[64];

  const int tid  = threadIdx.x;
  const int rank = blockIdx.x & (CLN-1);
  const int b0   = (blockIdx.x / CLN) * BPC;
  const int rg   = tid >> 4, kq = tid & 15;
  const float tauv = __ldg(&tau[0]), gamv = __ldg(&gam[0]);

  for (int i=tid; i<64*128; i+=256){
    int r=i>>7, q=i&127;
    float4 vc = __ldg((const float4*)&C1[(rank*64+r)*HID + q*4]);
    float4 vw = __ldg((const float4*)&W1[(rank*64+r)*HID + q*4]);
    __nv_bfloat162 c0 = __floats2bfloat162_rn(vc.x, vc.y);
    __nv_bfloat162 c1 = __floats2bfloat162_rn(vc.z, vc.w);
    __nv_bfloat162 w0 = __floats2bfloat162_rn(vw.x, vw.y);
    __nv_bfloat162 w1 = __floats2bfloat162_rn(vw.z, vw.w);
    uint2 uc; uc.x = *(uint32_t*)&c0; uc.y = *(uint32_t*)&c1;
    uint2 uw; uw.x = *(uint32_t*)&w0; uw.y = *(uint32_t*)&w1;
    *(uint2*)(wsmC + (unsigned)r*WROWB + (unsigned)q*8u) = uc;
    *(uint2*)(wsmW + (unsigned)r*WROWB + (unsigned)q*8u) = uw;
  }
  for (int i=tid;i<BPC*HID;i+=256) (&hbufP[0][0])[i]=0.f;
  if (tid<2*BPC) (&normloc[0][0])[tid]=0.f;
  if (tid<64)  sa[tid] = sigm(__ldg(&a1[rank*64+tid]));
  __syncthreads();

  const uint32_t a_ebuf = smem_u32(&ebufP[0][0]);
  const uint32_t a_hbuf = smem_u32(&hbufP[0][0]);
  const uint32_t a_narr = smem_u32(&narr[0][0]);

  const int eb = tid & 1, erow = tid >> 1;             // epilogue mapping (tid<128)
  const int dest = tid >> 5, chunk = tid & 31;         // push mapping (256 threads)
  const int pb = chunk >> 4, pq = chunk & 15;
  const uint32_t e_off = (uint32_t)(pb*HID + xpos(rank*16 + pq)*4)*4u;
  const int hk   = rank*64 + erow;
  const int hidx = eb*HID + xpos(hk>>2)*4 + (hk&3);

  float xsv=1.f, be0v=0.f, be1v=0.f;
  if (tid<128){
    int bb = b0+eb;
    xsv  = __ldg(&g_xs1[bb*TT]);
    be0v = __ldg(&g_be0[(bb*TT)*HID + rank*64 + erow]);
  }

  for (int t=0;t<TT;t++){
    const int par = t&1;

    {
      float acc[8];
      dot_bf16(wsmC, (const uint8_t*)&hbufP[0][0], rg, kq, acc);
      #pragma unroll
      for (int off=8; off; off>>=1)
        #pragma unroll
        for (int j=0;j<8;j++) acc[j] += __shfl_down_sync(0xffffffffu, acc[j], off);
      if (kq==0){
        #pragma unroll
        for (int j=0;j<4;j++) pout2[rg*4+j] = make_float2(acc[j*2], acc[j*2+1]);
      }
    }
    __syncthreads();
    if (tid<128){
      float pv = eb ? pout2[erow].y : pout2[erow].x;
      float p = tanhf(pv) * xsv;
      float e = be0v - p;
      estageP[eb][erow] = e;
      float q = e*e;
      #pragma unroll
      for (int off=16; off>=2; off>>=1) q += __shfl_xor_sync(0xffffffffu,q,off);
      if ((tid&31)<2) atomicAdd(&normloc[par][tid&1], q);
    }
    __syncthreads();
    {
      float4 v = ((const float4*)estageP)[chunk];
      dsmem_st4(a_ebuf + e_off, (uint32_t)dest, v);
      if (tid<16)
        dsmem_st1(a_narr + (uint32_t)(((tid&1)*CLN + rank)*4), (uint32_t)(tid>>1),
                  normloc[par][tid&1]);
    }
    CLUSTER_ARRIVE();
    if (tid<128)
      be1v = __ldg(&g_be1[((b0+eb)*TT+t)*HID + rank*64 + erow]);
    CLUSTER_WAIT();

    {
      float acc[8];
      dot_bf16(wsmW, (const uint8_t*)&ebufP[0][0], rg, kq, acc);
      #pragma unroll
      for (int off=8; off; off>>=1)
        #pragma unroll
        for (int j=0;j<8;j++) acc[j] += __shfl_down_sync(0xffffffffu, acc[j], off);
      if (kq==0){
        #pragma unroll
        for (int j=0;j<4;j++) pout2[rg*4+j] = make_float2(acc[j*2], acc[j*2+1]);
      }
    }
    __syncthreads();
    if (tid<128){
      float n2 = (narr[eb][0]+narr[eb][1])+(narr[eb][2]+narr[eb][3])
               + (narr[eb][4]+narr[eb][5])+(narr[eb][6]+narr[eb][7]);
      float rel = fminf(sqrtf(n2)/xsv, 4.0f);
      float s = sigm((rel - tauv)/gamv);
      float hold = (&hbufP[0][0])[hidx];
      float eev = eb ? pout2[erow].y : pout2[erow].x;
      float ih = 0.2f*hold + 0.6f*be1v + 0.2f*s*eev;
      float g = s*sa[erow];
      float hn = hold*(1.f-g) + tanhf(ih)*g;
      hstageP[eb][erow] = hn;
      g_h1[((b0+eb)*TT+t)*HID + rank*64 + erow] = hn;
      if (tid<2) normloc[par^1][tid] = 0.f;
    }
    __syncthreads();
    {
      float4 v = ((const float4*)hstageP)[chunk];
      dsmem_st4(a_hbuf + e_off, (uint32_t)dest, v);
    }
    CLUSTER_ARRIVE();
    if (tid<128 && t+1<TT){
      int bb = b0+eb;
      xsv  = __ldg(&g_xs1[bb*TT+t+1]);
      be0v = __ldg(&g_be0[(bb*TT+t+1)*HID + rank*64 + erow]);
    }
    CLUSTER_WAIT();
  }
}

// ---------------- head: 32 rows/block, f32x2, x staged in dynamic smem ------------
__global__ __launch_bounds__(256) void k_head(const float* __restrict__ hw,
                                              const float* __restrict__ hb,
                                              float* __restrict__ out){
  extern __shared__ __align__(16) float sh[];        // [HROWS][1024]
  __shared__ float sred[4][HROWS][64];
  int tid=threadIdx.x;
  int row0=blockIdx.x*HROWS;
  for (int i=tid;i<HROWS*256;i+=256){                // float4 granularity
    int r=i>>8, j4=i&255;
    float4 v;
    if (j4<128) v = *(const float4*)&g_h1 [(row0+r)*HID + j4*4];
    else        v = *(const float4*)&g_be1[(row0+r)*HID + (j4-128)*4];
    ((float4*)sh)[i] = v;
  }
  __syncthreads();
  int c=tid&63, q=tid>>6;
  unsigned long long acc[HROWS];
  #pragma unroll
  for (int r=0;r<HROWS;r++) acc[r]=0ull;
  const float* wrow = &hw[c*1024 + q*256];
  for (int k4=0;k4<64;k4++){
    ulonglong2 wp = *(const ulonglong2*)(wrow + k4*4);
    #pragma unroll
    for (int r=0;r<HROWS;r++){
      ulonglong2 xp = *(const ulonglong2*)&sh[r*1024 + q*256 + k4*4];
      ffma2(acc[r], wp.x, xp.x); ffma2(acc[r], wp.y, xp.y);
    }
  }
  #pragma unroll
  for (int r=0;r<HROWS;r++) sred[q][r][c]=hsum2(acc[r]);
  __syncthreads();
  for (int i=tid;i<HROWS*64;i+=256){
    int r=i>>6, cc=i&63;
    out[(row0+r)*NCLS+cc] = sred[0][r][cc]+sred[1][r][cc]
                          + sred[2][r][cc]+sred[3][r][cc] + __ldg(&hb[cc]);
  }
}

// ---------------- launch ----------------
extern "C" void kernel_launch(void* const* d_in, const int* in_sizes, int n_in,
                              void* d_out, int out_size){
  const float* feats=(const float*)d_in[0];
  const float* B0  =(const float*)d_in[2];
  const float* C1  =(const float*)d_in[7];
  const float* B1  =(const float*)d_in[8];
  const float* W1  =(const float*)d_in[9];
  const float* a1  =(const float*)d_in[10];
  const float* tau1=(const float*)d_in[11];
  const float* gam1=(const float*)d_in[12];
  const float* hw  =(const float*)d_in[13];
  const float* hb  =(const float*)d_in[14];
  float* out=(float*)d_out;

  static int smem_set = 0;
  if (!smem_set){
    cudaFuncSetAttribute(k_serial, cudaFuncAttributeMaxDynamicSharedMemorySize, DYNSM);
    cudaFuncSetAttribute(k_head,   cudaFuncAttributeMaxDynamicSharedMemorySize, HEAD_DYN);
    smem_set = 1;
  }

  k_be0   <<<NROW/16,256>>>(feats,B0);
  k_be1   <<<NROW/16,256>>>(B1);
  k_serial<<<NCTA,256,DYNSM>>>(C1,W1,a1,tau1,gam1);
  k_head  <<<NROW/HROWS,256,HEAD_DYN>>>(hw,hb,out);
}